// round 4
// baseline (speedup 1.0000x reference)
#include <cuda_runtime.h>
#include <cuda_bf16.h>
#include <math.h>
#include <stdint.h>

#define BATCH 4
#define SLEN 2048
#define DM 2048
#define NHEAD 16
#define HS 128
#define EPROJ (3 * DM)
#define KDIM 2048

// Scratch (no allocations allowed)
__device__ float g_q[(size_t)BATCH * NHEAD * SLEN * HS];
__device__ float g_attn[(size_t)BATCH * SLEN * DM];
// Pre-split bf16 hi/lo operands
__device__ __nv_bfloat16 g_xhi[(size_t)BATCH * SLEN * DM];
__device__ __nv_bfloat16 g_xlo[(size_t)BATCH * SLEN * DM];
__device__ __nv_bfloat16 g_wphi[(size_t)EPROJ * DM];
__device__ __nv_bfloat16 g_wplo[(size_t)EPROJ * DM];
__device__ __nv_bfloat16 g_wfhi[(size_t)DM * DM];
__device__ __nv_bfloat16 g_wflo[(size_t)DM * DM];
__device__ __nv_bfloat16 g_athi[(size_t)BATCH * SLEN * DM];
__device__ __nv_bfloat16 g_atlo[(size_t)BATCH * SLEN * DM];

// ---------------------------------------------------------------------------
// helpers (non-arch-specific PTX only)
// ---------------------------------------------------------------------------
__device__ __forceinline__ uint32_t smem_u32(const void* p) {
    uint32_t a;
    asm("{ .reg .u64 t; cvta.to.shared.u64 t, %1; cvt.u32.u64 %0, t; }"
        : "=r"(a) : "l"(p));
    return a;
}

__device__ __forceinline__ void ldm_x4(uint32_t* r, uint32_t addr) {
    asm volatile("ldmatrix.sync.aligned.m8n8.x4.shared.b16 {%0,%1,%2,%3}, [%4];"
                 : "=r"(r[0]), "=r"(r[1]), "=r"(r[2]), "=r"(r[3]) : "r"(addr));
}

__device__ __forceinline__ void mma_bf16(float* c, const uint32_t* a,
                                         const uint32_t* b) {
    asm volatile(
        "mma.sync.aligned.m16n8k16.row.col.f32.bf16.bf16.f32 "
        "{%0,%1,%2,%3}, {%4,%5,%6,%7}, {%8,%9}, {%0,%1,%2,%3};"
        : "+f"(c[0]), "+f"(c[1]), "+f"(c[2]), "+f"(c[3])
        : "r"(a[0]), "r"(a[1]), "r"(a[2]), "r"(a[3]), "r"(b[0]), "r"(b[1]));
}

#define CP_ASYNC16(dst, src) \
    asm volatile("cp.async.cg.shared.global [%0], [%1], 16;" \
                 :: "r"(dst), "l"(src))
#define CP_COMMIT() asm volatile("cp.async.commit_group;" ::: "memory")
#define CP_WAIT1() asm volatile("cp.async.wait_group 1;" ::: "memory")

__device__ __forceinline__ void split4(float4 v, uint2& hi, uint2& lo) {
    __nv_bfloat162 h01 = __floats2bfloat162_rn(v.x, v.y);
    __nv_bfloat162 h23 = __floats2bfloat162_rn(v.z, v.w);
    uint32_t u01 = *(uint32_t*)&h01, u23 = *(uint32_t*)&h23;
    float fx = __uint_as_float(u01 << 16);
    float fy = __uint_as_float(u01 & 0xffff0000u);
    float fz = __uint_as_float(u23 << 16);
    float fw = __uint_as_float(u23 & 0xffff0000u);
    __nv_bfloat162 l01 = __floats2bfloat162_rn(v.x - fx, v.y - fy);
    __nv_bfloat162 l23 = __floats2bfloat162_rn(v.z - fz, v.w - fw);
    hi = make_uint2(u01, u23);
    lo = make_uint2(*(uint32_t*)&l01, *(uint32_t*)&l23);
}

// fp32 -> bf16 hi/lo pre-split
__global__ __launch_bounds__(256) void split_kernel(
    const float4* __restrict__ src, uint2* __restrict__ hi,
    uint2* __restrict__ lo, int n4)
{
    int i = blockIdx.x * 256 + threadIdx.x;
    const int stride = gridDim.x * 256;
    for (; i < n4; i += stride) {
        uint2 h, l;
        split4(src[i], h, l);
        hi[i] = h;
        lo[i] = l;
    }
}

// ---------------------------------------------------------------------------
// Pipelined bf16-split GEMM: C = A * W^T + bias  (A,W pre-split hi/lo bf16)
// CTA 128x128, 8 warps (2Mx4N), warp tile 64x32, BK=32 bf16, 3-stage cp.async.
// smem stage: Ahi|Alo|Whi|Wlo, each 128 rows x 32 cols, pitch 40 bf16 (80B).
// ---------------------------------------------------------------------------
#define PITCHB 80                      // bytes per smem row
#define ARR_B (128 * PITCHB)           // 10240 B per array
#define STAGE_B (4 * ARR_B)            // 40960 B per stage
#define NSTAGE 3
#define GEMM_SMEM (NSTAGE * STAGE_B)   // 122880 B
#define NCHUNK (KDIM / 32)             // 64

template <int EPI>
__global__ __launch_bounds__(256) void gemm_bf_kernel(
    const __nv_bfloat16* __restrict__ Ahi, const __nv_bfloat16* __restrict__ Alo,
    const __nv_bfloat16* __restrict__ Whi, const __nv_bfloat16* __restrict__ Wlo,
    const float* __restrict__ bias, float* __restrict__ C,
    float* __restrict__ kout, float* __restrict__ vout)
{
    extern __shared__ __align__(16) char smem[];
    const uint32_t sbase = smem_u32(smem);

    const int tid = threadIdx.x;
    const int wid = tid >> 5;
    const int lid = tid & 31;
    const int m0 = blockIdx.y * 128;
    const int n0 = blockIdx.x * 128;
    const int warpM = wid >> 2;
    const int warpN = wid & 3;

    // cp.async mapping: 4 arrays x 128 rows; thread -> (array, 2 rows, 4 chunks)
    const int arr = tid >> 6;
    const int r0 = (tid & 63) << 1;
    const __nv_bfloat16* srcb;
    if (arr == 0)      srcb = Ahi + (size_t)(m0 + r0) * KDIM;
    else if (arr == 1) srcb = Alo + (size_t)(m0 + r0) * KDIM;
    else if (arr == 2) srcb = Whi + (size_t)(n0 + r0) * KDIM;
    else               srcb = Wlo + (size_t)(n0 + r0) * KDIM;
    const uint32_t dst0 = sbase + (uint32_t)(arr * ARR_B + r0 * PITCHB);

    // ldmatrix lane offsets (bytes, within a stage)
    const int q = lid >> 3, rr = lid & 7;
    const uint32_t aoff = (uint32_t)((warpM * 64 + (q & 1) * 8 + rr) * PITCHB +
                                     (q >> 1) * 16);
    const uint32_t boff = (uint32_t)((warpN * 32 + (q >> 1) * 8 + rr) * PITCHB +
                                     (q & 1) * 16);

    float acc[4][4][4];
#pragma unroll
    for (int i = 0; i < 4; i++)
#pragma unroll
        for (int j = 0; j < 4; j++)
#pragma unroll
            for (int r = 0; r < 4; r++) acc[i][j][r] = 0.f;

    // prologue: stages 0, 1
#pragma unroll
    for (int s = 0; s < 2; s++) {
        const uint32_t d = dst0 + s * STAGE_B;
        const __nv_bfloat16* sp = srcb + s * 32;
#pragma unroll
        for (int rw = 0; rw < 2; rw++)
#pragma unroll
            for (int c4 = 0; c4 < 4; c4++)
                CP_ASYNC16(d + rw * PITCHB + c4 * 16, sp + rw * KDIM + c4 * 8);
        CP_COMMIT();
    }

    for (int c = 0; c < NCHUNK; c++) {
        CP_WAIT1();
        __syncthreads();

        if (c + 2 < NCHUNK) {
            const uint32_t d = dst0 + ((c + 2) % NSTAGE) * STAGE_B;
            const __nv_bfloat16* sp = srcb + (c + 2) * 32;
#pragma unroll
            for (int rw = 0; rw < 2; rw++)
#pragma unroll
                for (int c4 = 0; c4 < 4; c4++)
                    CP_ASYNC16(d + rw * PITCHB + c4 * 16, sp + rw * KDIM + c4 * 8);
        }
        CP_COMMIT();

        const uint32_t st = sbase + (c % NSTAGE) * STAGE_B;
#pragma unroll
        for (int ks = 0; ks < 2; ks++) {
            const uint32_t kb = (uint32_t)(ks * 32);
            uint32_t ah[4][4], al[4][4], bh[2][4], bl[2][4];
#pragma unroll
            for (int mi = 0; mi < 4; mi++) {
                const uint32_t off = aoff + (uint32_t)(mi * 16 * PITCHB) + kb;
                ldm_x4(ah[mi], st + off);
                ldm_x4(al[mi], st + ARR_B + off);
            }
#pragma unroll
            for (int pj = 0; pj < 2; pj++) {
                const uint32_t off = boff + (uint32_t)(pj * 16 * PITCHB) + kb;
                ldm_x4(bh[pj], st + 2 * ARR_B + off);
                ldm_x4(bl[pj], st + 3 * ARR_B + off);
            }
#pragma unroll
            for (int mi = 0; mi < 4; mi++)
#pragma unroll
                for (int nj = 0; nj < 4; nj++) {
                    const uint32_t* bhp = &bh[nj >> 1][(nj & 1) * 2];
                    const uint32_t* blp = &bl[nj >> 1][(nj & 1) * 2];
                    mma_bf16(acc[mi][nj], ah[mi], bhp);
                    mma_bf16(acc[mi][nj], al[mi], bhp);
                    mma_bf16(acc[mi][nj], ah[mi], blp);
                }
        }
        __syncthreads();
    }

    // Epilogue
    const int t4 = lid >> 2;
    const int t2 = (lid & 3) << 1;
#pragma unroll
    for (int mi = 0; mi < 4; mi++) {
        const int mrow = m0 + warpM * 64 + mi * 16 + t4;
        float *d0, *d1;
        if (EPI == 1) {
            const int seg = n0 >> 7;
            const int h = (int)((unsigned)seg / 3u);
            const int which = seg - h * 3;
            float* base = (which == 0) ? g_q : ((which == 1) ? kout : vout);
            const int b0i = mrow >> 11, s0i = mrow & 2047;
            const int b1i = (mrow + 8) >> 11, s1i = (mrow + 8) & 2047;
            d0 = base + (((size_t)(b0i * NHEAD + h)) * SLEN + s0i) * HS;
            d1 = base + (((size_t)(b1i * NHEAD + h)) * SLEN + s1i) * HS;
        } else {
            d0 = C + (size_t)mrow * DM + n0;
            d1 = C + (size_t)(mrow + 8) * DM + n0;
        }
#pragma unroll
        for (int nj = 0; nj < 4; nj++) {
            const int col = warpN * 32 + nj * 8 + t2;
            const float2 bb = *(const float2*)(bias + n0 + col);
            float2 v0 = make_float2(acc[mi][nj][0] + bb.x, acc[mi][nj][1] + bb.y);
            float2 v1 = make_float2(acc[mi][nj][2] + bb.x, acc[mi][nj][3] + bb.y);
            *(float2*)(d0 + col) = v0;
            *(float2*)(d1 + col) = v1;
        }
    }
}

// ---------------------------------------------------------------------------
// Flash attention (fp32 SIMT), causal — unchanged.
// ---------------------------------------------------------------------------
#define ATTN_SMEM_FLOATS (64 * 128 + 64 * 128 + 64 * 65 + 192)
#define ATTN_SMEM_BYTES (ATTN_SMEM_FLOATS * 4)

__global__ __launch_bounds__(256) void attn_kernel(
    const float* __restrict__ Kg, const float* __restrict__ Vg)
{
    extern __shared__ float sm[];
    float* Qs  = sm;
    float* KVs = sm + 8192;
    float* Ss  = sm + 16384;
    float* m_s = Ss + 64 * 65;
    float* l_s = m_s + 64;
    float* a_s = l_s + 64;

    const int qt  = blockIdx.x;
    const int bh  = blockIdx.y;
    const int tid = threadIdx.x;
    const int tr  = tid >> 4;
    const int tc  = tid & 15;

    const float* Qb = g_q + (size_t)bh * SLEN * HS + (size_t)qt * 64 * HS;
    const float* Kb = Kg + (size_t)bh * SLEN * HS;
    const float* Vb = Vg + (size_t)bh * SLEN * HS;

    const float scale = 0.08838834764831845f;
    for (int i = tid; i < 64 * 32; i += 256) {
        float4 v = ((const float4*)Qb)[i];
        v.x *= scale; v.y *= scale; v.z *= scale; v.w *= scale;
        ((float4*)Qs)[i] = v;
    }
    if (tid < 64) { m_s[tid] = -INFINITY; l_s[tid] = 0.f; }

    float o[4][8];
#pragma unroll
    for (int i = 0; i < 4; i++)
#pragma unroll
        for (int j = 0; j < 8; j++) o[i][j] = 0.f;

    for (int kt = 0; kt <= qt; kt++) {
        __syncthreads();
        const float4* Kt = (const float4*)(Kb + (size_t)kt * 64 * HS);
        for (int i = tid; i < 64 * 32; i += 256) ((float4*)KVs)[i] = Kt[i];
        __syncthreads();

        float s4[4][4];
#pragma unroll
        for (int i = 0; i < 4; i++)
#pragma unroll
            for (int j = 0; j < 4; j++) s4[i][j] = 0.f;

#pragma unroll 4
        for (int d = 0; d < 128; d += 4) {
            float4 qv[4], kv[4];
#pragma unroll
            for (int i = 0; i < 4; i++)
                qv[i] = *(const float4*)(Qs + (tr * 4 + i) * 128 + d);
#pragma unroll
            for (int j = 0; j < 4; j++)
                kv[j] = *(const float4*)(KVs + (tc * 4 + j) * 128 + d);
#pragma unroll
            for (int i = 0; i < 4; i++)
#pragma unroll
                for (int j = 0; j < 4; j++) {
                    s4[i][j] = fmaf(qv[i].x, kv[j].x, s4[i][j]);
                    s4[i][j] = fmaf(qv[i].y, kv[j].y, s4[i][j]);
                    s4[i][j] = fmaf(qv[i].z, kv[j].z, s4[i][j]);
                    s4[i][j] = fmaf(qv[i].w, kv[j].w, s4[i][j]);
                }
        }

        const bool diag = (kt == qt);
#pragma unroll
        for (int i = 0; i < 4; i++)
#pragma unroll
            for (int j = 0; j < 4; j++) {
                const int r = tr * 4 + i, c = tc * 4 + j;
                float v = s4[i][j];
                if (diag && c > r) v = -INFINITY;
                Ss[r * 65 + c] = v;
            }
        __syncthreads();

        const float4* Vt = (const float4*)(Vb + (size_t)kt * 64 * HS);
        for (int i = tid; i < 64 * 32; i += 256) ((float4*)KVs)[i] = Vt[i];

        if (tid < 64) {
            const int r = tid;
            const float mold = m_s[r];
            float mnew = mold;
#pragma unroll 8
            for (int c = 0; c < 64; c++) mnew = fmaxf(mnew, Ss[r * 65 + c]);
            const float alpha = __expf(mold - mnew);
            float lsum = 0.f;
#pragma unroll 8
            for (int c = 0; c < 64; c++) {
                const float p = __expf(Ss[r * 65 + c] - mnew);
                Ss[r * 65 + c] = p;
                lsum += p;
            }
            l_s[r] = l_s[r] * alpha + lsum;
            m_s[r] = mnew;
            a_s[r] = alpha;
        }
        __syncthreads();

#pragma unroll
        for (int i = 0; i < 4; i++) {
            const float al = a_s[tr * 4 + i];
#pragma unroll
            for (int j = 0; j < 8; j++) o[i][j] *= al;
        }
#pragma unroll 4
        for (int k = 0; k < 64; k++) {
            const float4 v0 = *(const float4*)(KVs + k * 128 + tc * 8);
            const float4 v1 = *(const float4*)(KVs + k * 128 + tc * 8 + 4);
#pragma unroll
            for (int i = 0; i < 4; i++) {
                const float p = Ss[(tr * 4 + i) * 65 + k];
                o[i][0] = fmaf(p, v0.x, o[i][0]);
                o[i][1] = fmaf(p, v0.y, o[i][1]);
                o[i][2] = fmaf(p, v0.z, o[i][2]);
                o[i][3] = fmaf(p, v0.w, o[i][3]);
                o[i][4] = fmaf(p, v1.x, o[i][4]);
                o[i][5] = fmaf(p, v1.y, o[i][5]);
                o[i][6] = fmaf(p, v1.z, o[i][6]);
                o[i][7] = fmaf(p, v1.w, o[i][7]);
            }
        }
    }

    const int b = bh >> 4, h = bh & 15;
#pragma unroll
    for (int i = 0; i < 4; i++) {
        const int r = tr * 4 + i;
        const float inv = 1.f / l_s[r];
        float* dst = g_attn + ((size_t)(b * SLEN + qt * 64 + r)) * DM + h * HS + tc * 8;
        float4 w0 = make_float4(o[i][0] * inv, o[i][1] * inv, o[i][2] * inv, o[i][3] * inv);
        float4 w1 = make_float4(o[i][4] * inv, o[i][5] * inv, o[i][6] * inv, o[i][7] * inv);
        *(float4*)dst = w0;
        *(float4*)(dst + 4) = w1;
    }
}

// ---------------------------------------------------------------------------
extern "C" void kernel_launch(void* const* d_in, const int* in_sizes, int n_in,
                              void* d_out, int out_size)
{
    const float* x      = (const float*)d_in[0];
    const float* w_proj = (const float*)d_in[1];
    const float* b_proj = (const float*)d_in[2];
    const float* w_ff   = (const float*)d_in[3];
    const float* b_ff   = (const float*)d_in[4];

    float* out = (float*)d_out;
    float* ff   = out;
    float* kout = out + (size_t)BATCH * SLEN * DM;
    float* vout = kout + (size_t)BATCH * NHEAD * SLEN * HS;

    cudaFuncSetAttribute(attn_kernel,
                         cudaFuncAttributeMaxDynamicSharedMemorySize, ATTN_SMEM_BYTES);
    cudaFuncSetAttribute(gemm_bf_kernel<1>,
                         cudaFuncAttributeMaxDynamicSharedMemorySize, GEMM_SMEM);
    cudaFuncSetAttribute(gemm_bf_kernel<2>,
                         cudaFuncAttributeMaxDynamicSharedMemorySize, GEMM_SMEM);

    __nv_bfloat16 *xhi, *xlo, *wphi, *wplo, *wfhi, *wflo, *athi, *atlo;
    cudaGetSymbolAddress((void**)&xhi, g_xhi);
    cudaGetSymbolAddress((void**)&xlo, g_xlo);
    cudaGetSymbolAddress((void**)&wphi, g_wphi);
    cudaGetSymbolAddress((void**)&wplo, g_wplo);
    cudaGetSymbolAddress((void**)&wfhi, g_wfhi);
    cudaGetSymbolAddress((void**)&wflo, g_wflo);
    cudaGetSymbolAddress((void**)&athi, g_athi);
    cudaGetSymbolAddress((void**)&atlo, g_atlo);
    float* attn_f;
    cudaGetSymbolAddress((void**)&attn_f, g_attn);

    // 0) pre-split fp32 -> bf16 hi/lo
    const int n4x = (BATCH * SLEN * DM) / 4;        // 4.19M
    const int n4wp = (EPROJ * DM) / 4;              // 3.15M
    const int n4wf = (DM * DM) / 4;                 // 1.05M
    split_kernel<<<4096, 256>>>((const float4*)x, (uint2*)xhi, (uint2*)xlo, n4x);
    split_kernel<<<4096, 256>>>((const float4*)w_proj, (uint2*)wphi, (uint2*)wplo, n4wp);
    split_kernel<<<2048, 256>>>((const float4*)w_ff, (uint2*)wfhi, (uint2*)wflo, n4wf);

    // 1) QKV projection
    gemm_bf_kernel<1><<<dim3(EPROJ / 128, (BATCH * SLEN) / 128), 256, GEMM_SMEM>>>(
        xhi, xlo, wphi, wplo, b_proj, (float*)nullptr, kout, vout);

    // 2) Causal flash attention -> g_attn
    attn_kernel<<<dim3(SLEN / 64, BATCH * NHEAD), 256, ATTN_SMEM_BYTES>>>(kout, vout);

    // 2b) split attn output
    split_kernel<<<4096, 256>>>((const float4*)attn_f, (uint2*)athi, (uint2*)atlo, n4x);

    // 3) FF projection
    gemm_bf_kernel<2><<<dim3(DM / 128, (BATCH * SLEN) / 128), 256, GEMM_SMEM>>>(
        athi, atlo, wfhi, wflo, b_ff, ff, (float*)nullptr, (float*)nullptr);
}

// round 5
// speedup vs baseline: 2.9477x; 2.9477x over previous
#include <cuda_runtime.h>
#include <cuda_bf16.h>
#include <math.h>
#include <stdint.h>

#define BATCH 4
#define SLEN 2048
#define DM 2048
#define NHEAD 16
#define HS 128
#define EPROJ (3 * DM)
#define KDIM 2048

// Scratch (no allocations allowed)
__device__ float g_attn[(size_t)BATCH * SLEN * DM];
__device__ __nv_bfloat16 g_qhi[(size_t)BATCH * NHEAD * SLEN * HS];
__device__ __nv_bfloat16 g_qlo[(size_t)BATCH * NHEAD * SLEN * HS];
__device__ __nv_bfloat16 g_khi[(size_t)BATCH * NHEAD * SLEN * HS];
__device__ __nv_bfloat16 g_klo[(size_t)BATCH * NHEAD * SLEN * HS];
__device__ __nv_bfloat16 g_vhi[(size_t)BATCH * NHEAD * SLEN * HS];
__device__ __nv_bfloat16 g_vlo[(size_t)BATCH * NHEAD * SLEN * HS];

// ---------------------------------------------------------------------------
// helpers (non-arch-specific PTX only)
// ---------------------------------------------------------------------------
__device__ __forceinline__ uint32_t smem_u32(const void* p) {
    uint32_t a;
    asm("{ .reg .u64 t; cvta.to.shared.u64 t, %1; cvt.u32.u64 %0, t; }"
        : "=r"(a) : "l"(p));
    return a;
}

__device__ __forceinline__ void ldm_x4(uint32_t* r, uint32_t addr) {
    asm volatile("ldmatrix.sync.aligned.m8n8.x4.shared.b16 {%0,%1,%2,%3}, [%4];"
                 : "=r"(r[0]), "=r"(r[1]), "=r"(r[2]), "=r"(r[3]) : "r"(addr));
}

__device__ __forceinline__ void ldm_x4_t(uint32_t* r, uint32_t addr) {
    asm volatile("ldmatrix.sync.aligned.m8n8.x4.trans.shared.b16 {%0,%1,%2,%3}, [%4];"
                 : "=r"(r[0]), "=r"(r[1]), "=r"(r[2]), "=r"(r[3]) : "r"(addr));
}

__device__ __forceinline__ void mma_bf16(float* c, const uint32_t* a,
                                         const uint32_t* b) {
    asm volatile(
        "mma.sync.aligned.m16n8k16.row.col.f32.bf16.bf16.f32 "
        "{%0,%1,%2,%3}, {%4,%5,%6,%7}, {%8,%9}, {%0,%1,%2,%3};"
        : "+f"(c[0]), "+f"(c[1]), "+f"(c[2]), "+f"(c[3])
        : "r"(a[0]), "r"(a[1]), "r"(a[2]), "r"(a[3]), "r"(b[0]), "r"(b[1]));
}

#define CP_ASYNC16(dst, src) \
    asm volatile("cp.async.cg.shared.global [%0], [%1], 16;" \
                 :: "r"(dst), "l"(src))
#define CP_COMMIT() asm volatile("cp.async.commit_group;" ::: "memory")
#define CP_WAIT1() asm volatile("cp.async.wait_group 1;" ::: "memory")
#define CP_WAIT0() asm volatile("cp.async.wait_group 0;" ::: "memory")

__device__ __forceinline__ void split4(float4 v, uint2& hi, uint2& lo) {
    __nv_bfloat162 h01 = __floats2bfloat162_rn(v.x, v.y);
    __nv_bfloat162 h23 = __floats2bfloat162_rn(v.z, v.w);
    uint32_t u01 = *(uint32_t*)&h01, u23 = *(uint32_t*)&h23;
    float fx = __uint_as_float(u01 << 16);
    float fy = __uint_as_float(u01 & 0xffff0000u);
    float fz = __uint_as_float(u23 << 16);
    float fw = __uint_as_float(u23 & 0xffff0000u);
    __nv_bfloat162 l01 = __floats2bfloat162_rn(v.x - fx, v.y - fy);
    __nv_bfloat162 l23 = __floats2bfloat162_rn(v.z - fz, v.w - fw);
    hi = make_uint2(u01, u23);
    lo = make_uint2(*(uint32_t*)&l01, *(uint32_t*)&l23);
}

// ---------------------------------------------------------------------------
// mma.sync bf16-split GEMM (R3 form): C = A * W^T + bias
// CTA 128x128, 8 warps (2Mx4N), warp tile 64x32, BK=32, in-kernel fp32 split.
// EPI==1: QKV epilogue -> q(scaled) hi/lo scratch, k/v fp32 d_out + hi/lo.
// EPI==2: dense C (A = g_attn).
// ---------------------------------------------------------------------------
#define PITCH 40
#define TILE_E (128 * PITCH)
#define AHI 0
#define ALO TILE_E
#define WHI (2 * TILE_E)
#define WLO (3 * TILE_E)

template <int EPI>
__global__ __launch_bounds__(256) void gemm_mma_kernel(
    const float* __restrict__ Ain, const float* __restrict__ W,
    const float* __restrict__ bias, float* __restrict__ C,
    float* __restrict__ kout, float* __restrict__ vout)
{
    __shared__ __align__(16) __nv_bfloat16 sm_bf[4 * TILE_E];

    const float* A = (EPI == 2) ? (const float*)g_attn : Ain;
    const int K = KDIM;
    const int tid = threadIdx.x;
    const int wid = tid >> 5;
    const int lid = tid & 31;
    const int m0 = blockIdx.y * 128;
    const int n0 = blockIdx.x * 128;
    const int warpM = wid >> 2;
    const int warpN = wid & 3;

    const uint32_t sbase = smem_u32(sm_bf);

    const int q = lid >> 3, rr = lid & 7;
    const uint32_t aAddr = sbase +
        (uint32_t)(((warpM * 64 + (q & 1) * 8 + rr) * PITCH + (q >> 1) * 8) * 2);
    const uint32_t bAddr = sbase +
        (uint32_t)(((warpN * 32 + (q >> 1) * 8 + rr) * PITCH + (q & 1) * 8) * 2);

    float acc[4][4][4];
#pragma unroll
    for (int i = 0; i < 4; i++)
#pragma unroll
        for (int j = 0; j < 4; j++)
#pragma unroll
            for (int r = 0; r < 4; r++) acc[i][j][r] = 0.f;

    const int srow = tid >> 1;
    const int scol = (tid & 1) << 4;
    const float* Aptr = A + (size_t)(m0 + srow) * K + scol;
    const float* Wptr = W + (size_t)(n0 + srow) * K + scol;
    const uint32_t sto = (uint32_t)(srow * PITCH + scol);

    float4 va[4], vw[4];
#pragma unroll
    for (int i = 0; i < 4; i++) {
        va[i] = *(const float4*)(Aptr + i * 4);
        vw[i] = *(const float4*)(Wptr + i * 4);
    }

    for (int c = 0; c < 64; c++) {
        __syncthreads();
#pragma unroll
        for (int i = 0; i < 4; i++) {
            uint2 hi, lo;
            split4(va[i], hi, lo);
            *(uint2*)((char*)sm_bf + (size_t)(AHI + sto + i * 4) * 2) = hi;
            *(uint2*)((char*)sm_bf + (size_t)(ALO + sto + i * 4) * 2) = lo;
            split4(vw[i], hi, lo);
            *(uint2*)((char*)sm_bf + (size_t)(WHI + sto + i * 4) * 2) = hi;
            *(uint2*)((char*)sm_bf + (size_t)(WLO + sto + i * 4) * 2) = lo;
        }
        if (c < 63) {
            const float* ap = Aptr + (c + 1) * 32;
            const float* wp = Wptr + (c + 1) * 32;
#pragma unroll
            for (int i = 0; i < 4; i++) {
                va[i] = *(const float4*)(ap + i * 4);
                vw[i] = *(const float4*)(wp + i * 4);
            }
        }
        __syncthreads();

#pragma unroll
        for (int ks = 0; ks < 2; ks++) {
            const uint32_t kb = (uint32_t)(ks * 32);
            uint32_t ah[4][4], al[4][4], bh[2][4], bl[2][4];
#pragma unroll
            for (int mi = 0; mi < 4; mi++) {
                const uint32_t off = (uint32_t)(mi * 16 * PITCH * 2) + kb;
                ldm_x4(ah[mi], aAddr + AHI * 2 + off);
                ldm_x4(al[mi], aAddr + ALO * 2 + off);
            }
#pragma unroll
            for (int pj = 0; pj < 2; pj++) {
                const uint32_t off = (uint32_t)(pj * 16 * PITCH * 2) + kb;
                ldm_x4(bh[pj], bAddr + WHI * 2 + off);
                ldm_x4(bl[pj], bAddr + WLO * 2 + off);
            }
#pragma unroll
            for (int mi = 0; mi < 4; mi++)
#pragma unroll
                for (int nj = 0; nj < 4; nj++) {
                    const uint32_t* bhp = &bh[nj >> 1][(nj & 1) * 2];
                    const uint32_t* blp = &bl[nj >> 1][(nj & 1) * 2];
                    mma_bf16(acc[mi][nj], ah[mi], bhp);
                    mma_bf16(acc[mi][nj], al[mi], bhp);
                    mma_bf16(acc[mi][nj], ah[mi], blp);
                }
        }
    }

    // Epilogue
    const int t4 = lid >> 2;
    const int t2 = (lid & 3) << 1;
    if (EPI == 1) {
        const int seg = n0 >> 7;
        const int h = (int)((unsigned)seg / 3u);
        const int which = seg - h * 3;
        __nv_bfloat16 *hib, *lob;
        float* fpb = nullptr;
        if (which == 0)      { hib = g_qhi; lob = g_qlo; }
        else if (which == 1) { hib = g_khi; lob = g_klo; fpb = kout; }
        else                 { hib = g_vhi; lob = g_vlo; fpb = vout; }
        const float scl = (which == 0) ? 0.08838834764831845f : 1.0f;
#pragma unroll
        for (int mi = 0; mi < 4; mi++) {
            const int mrow = m0 + warpM * 64 + mi * 16 + t4;
            const int bb = mrow >> 11, ss = mrow & 2047;
            const size_t i0 = (((size_t)(bb * NHEAD + h)) * SLEN + ss) * HS;
            const size_t i1 = i0 + 8 * HS;
#pragma unroll
            for (int nj = 0; nj < 4; nj++) {
                const int col = warpN * 32 + nj * 8 + t2;
                const float2 bv = *(const float2*)(bias + n0 + col);
                float x0 = acc[mi][nj][0] + bv.x, x1 = acc[mi][nj][1] + bv.y;
                float y0 = acc[mi][nj][2] + bv.x, y1 = acc[mi][nj][3] + bv.y;
                if (which != 0) {
                    *(float2*)(fpb + i0 + col) = make_float2(x0, x1);
                    *(float2*)(fpb + i1 + col) = make_float2(y0, y1);
                }
                x0 *= scl; x1 *= scl; y0 *= scl; y1 *= scl;
                __nv_bfloat162 hx = __floats2bfloat162_rn(x0, x1);
                float2 hf = __bfloat1622float2(hx);
                __nv_bfloat162 lx = __floats2bfloat162_rn(x0 - hf.x, x1 - hf.y);
                __nv_bfloat162 hy = __floats2bfloat162_rn(y0, y1);
                float2 hg = __bfloat1622float2(hy);
                __nv_bfloat162 ly = __floats2bfloat162_rn(y0 - hg.x, y1 - hg.y);
                *(__nv_bfloat162*)(hib + i0 + col) = hx;
                *(__nv_bfloat162*)(lob + i0 + col) = lx;
                *(__nv_bfloat162*)(hib + i1 + col) = hy;
                *(__nv_bfloat162*)(lob + i1 + col) = ly;
            }
        }
    } else {
#pragma unroll
        for (int mi = 0; mi < 4; mi++) {
            const int mrow = m0 + warpM * 64 + mi * 16 + t4;
            float* d0 = C + (size_t)mrow * DM + n0;
            float* d1 = C + (size_t)(mrow + 8) * DM + n0;
#pragma unroll
            for (int nj = 0; nj < 4; nj++) {
                const int col = warpN * 32 + nj * 8 + t2;
                const float2 bv = *(const float2*)(bias + n0 + col);
                *(float2*)(d0 + col) =
                    make_float2(acc[mi][nj][0] + bv.x, acc[mi][nj][1] + bv.y);
                *(float2*)(d1 + col) =
                    make_float2(acc[mi][nj][2] + bv.x, acc[mi][nj][3] + bv.y);
            }
        }
    }
}

// ---------------------------------------------------------------------------
// Flash attention via mma.sync (FA2-style), causal, bf16 2-way split on both
// QK^T and PV. CTA = 128 q-rows x one (b*H+h); 8 warps x m16; KV tiles of 64,
// cp.async double-buffered. Q/K/V smem rows = 256B with chunk-XOR swizzle.
// ---------------------------------------------------------------------------
#define QT 128
#define KT 64
#define Q_BYTES 32768                      // 128 rows * 256B
#define KV_ARR 16384                       // 64 rows * 256B
#define KV_BUF (4 * KV_ARR)                // khi,klo,vhi,vlo
#define ATT_SMEM (2 * Q_BYTES + 2 * KV_BUF)  // 196608

__device__ __forceinline__ uint32_t swz(int row, int chunk) {
    return (uint32_t)(row * 256 + ((chunk ^ (row & 7)) << 4));
}

__global__ __launch_bounds__(256) void attn_mma_kernel()
{
    extern __shared__ __align__(16) char sm[];
    const uint32_t sb = smem_u32(sm);
    const int tid = threadIdx.x, wid = tid >> 5, lane = tid & 31;
    const int qb = blockIdx.x, bh = blockIdx.y;
    const int q0 = qb * QT;
    const int nkt = 2 * qb + 2;

    const size_t qoff = ((size_t)bh * SLEN + q0) * HS;
    const size_t kvoff = (size_t)bh * SLEN * HS;

    // Q load (LDG -> swizzled STS)
    {
        const int half = tid >> 7;  // 0: hi, 1: lo
        const __nv_bfloat16* src = (half ? g_qlo : g_qhi) + qoff;
        char* base = sm + half * Q_BYTES;
        int rc = tid & 127;
#pragma unroll
        for (int t = 0; t < 16; t++, rc += 128) {
            const int row = rc >> 4, c = rc & 15;
            uint4 v = *(const uint4*)(src + row * HS + c * 8);
            *(uint4*)(base + swz(row, c)) = v;
        }
    }

    // KV cp.async: thread group (tid>>6) handles one of khi/klo/vhi/vlo
    const int karr = tid >> 6;
    const __nv_bfloat16* ksrc =
        ((karr == 0) ? g_khi : (karr == 1) ? g_klo : (karr == 2) ? g_vhi : g_vlo)
        + kvoff;
    const uint32_t kdstArr = sb + 2 * Q_BYTES + (uint32_t)(karr * KV_ARR);

    auto kv_issue = [&](int kt, int bf) {
        const __nv_bfloat16* s = ksrc + (size_t)kt * KT * HS;
        const uint32_t dbase = kdstArr + (uint32_t)(bf * KV_BUF);
        int rc = tid & 63;
#pragma unroll
        for (int t = 0; t < 16; t++, rc += 64) {
            const int row = rc >> 4, c = rc & 15;
            CP_ASYNC16(dbase + swz(row, c), s + row * HS + c * 8);
        }
    };

    kv_issue(0, 0);
    CP_COMMIT();

    float o[16][4];
#pragma unroll
    for (int t = 0; t < 16; t++)
#pragma unroll
        for (int r = 0; r < 4; r++) o[t][r] = 0.f;
    float m0r = -INFINITY, m1r = -INFINITY, l0r = 0.f, l1r = 0.f;

    // fragment address components
    const int aRow = wid * 16 + (lane & 7) + ((lane >> 3) & 1) * 8;  // Q rows
    const int aCh = lane >> 4;                                        // + 2*ks
    const int bRowK = (lane & 7) + (lane >> 4) * 8;                   // + njp*16
    const int bChK = (lane >> 3) & 1;                                 // + 2*ks
    const int vRow = (lane & 7) + ((lane >> 3) & 1) * 8;              // + j*16
    const int vCh = lane >> 4;                                        // + 2*nd

    for (int kt = 0; kt < nkt; kt++) {
        if (kt + 1 < nkt) {
            kv_issue(kt + 1, (kt + 1) & 1);
            CP_COMMIT();
            CP_WAIT1();
        } else {
            CP_WAIT0();
        }
        __syncthreads();

        const uint32_t kvb = sb + 2 * Q_BYTES + (uint32_t)((kt & 1) * KV_BUF);

        // ---- S = Qhi Khi^T + Qlo Khi^T + Qhi Klo^T ----
        float s[8][4];
#pragma unroll
        for (int nj = 0; nj < 8; nj++)
#pragma unroll
            for (int r = 0; r < 4; r++) s[nj][r] = 0.f;

#pragma unroll
        for (int ks = 0; ks < 8; ks++) {
            uint32_t qh[4], ql[4];
            const uint32_t qa = sb + swz(aRow, 2 * ks + aCh);
            ldm_x4(qh, qa);
            ldm_x4(ql, qa + Q_BYTES);
#pragma unroll
            for (int njp = 0; njp < 4; njp++) {
                uint32_t kh[4], kl[4];
                const uint32_t ka = kvb + swz(njp * 16 + bRowK, 2 * ks + bChK);
                ldm_x4(kh, ka);
                ldm_x4(kl, ka + KV_ARR);
                mma_bf16(s[2 * njp], qh, kh);
                mma_bf16(s[2 * njp], ql, kh);
                mma_bf16(s[2 * njp], qh, kl);
                mma_bf16(s[2 * njp + 1], qh, kh + 2);
                mma_bf16(s[2 * njp + 1], ql, kh + 2);
                mma_bf16(s[2 * njp + 1], qh, kl + 2);
            }
        }

        // ---- causal mask (only the last two tiles overlap the diagonal) ----
        const int r0g = q0 + wid * 16 + (lane >> 2);
        if (kt >= 2 * qb) {
            const int cb = kt * KT + (lane & 3) * 2;
#pragma unroll
            for (int nj = 0; nj < 8; nj++) {
                const int c0 = cb + nj * 8;
                if (c0 > r0g)       s[nj][0] = -INFINITY;
                if (c0 + 1 > r0g)   s[nj][1] = -INFINITY;
                if (c0 > r0g + 8)   s[nj][2] = -INFINITY;
                if (c0 + 1 > r0g + 8) s[nj][3] = -INFINITY;
            }
        }

        // ---- streaming softmax on fragments ----
        float tm0 = -INFINITY, tm1 = -INFINITY;
#pragma unroll
        for (int nj = 0; nj < 8; nj++) {
            tm0 = fmaxf(tm0, fmaxf(s[nj][0], s[nj][1]));
            tm1 = fmaxf(tm1, fmaxf(s[nj][2], s[nj][3]));
        }
        tm0 = fmaxf(tm0, __shfl_xor_sync(0xffffffffu, tm0, 1));
        tm0 = fmaxf(tm0, __shfl_xor_sync(0xffffffffu, tm0, 2));
        tm1 = fmaxf(tm1, __shfl_xor_sync(0xffffffffu, tm1, 1));
        tm1 = fmaxf(tm1, __shfl_xor_sync(0xffffffffu, tm1, 2));
        const float mn0 = fmaxf(m0r, tm0), mn1 = fmaxf(m1r, tm1);
        const float a0 = __expf(m0r - mn0), a1 = __expf(m1r - mn1);
        m0r = mn0; m1r = mn1;

        float ls0 = 0.f, ls1 = 0.f;
        uint32_t pah[4][4], pal[4][4];
#pragma unroll
        for (int nj = 0; nj < 8; nj++) {
            const float p0 = __expf(s[nj][0] - mn0);
            const float p1 = __expf(s[nj][1] - mn0);
            const float p2 = __expf(s[nj][2] - mn1);
            const float p3 = __expf(s[nj][3] - mn1);
            ls0 += p0 + p1;
            ls1 += p2 + p3;
            __nv_bfloat162 h01 = __floats2bfloat162_rn(p0, p1);
            float2 hf01 = __bfloat1622float2(h01);
            __nv_bfloat162 lo01 = __floats2bfloat162_rn(p0 - hf01.x, p1 - hf01.y);
            __nv_bfloat162 h23 = __floats2bfloat162_rn(p2, p3);
            float2 hf23 = __bfloat1622float2(h23);
            __nv_bfloat162 lo23 = __floats2bfloat162_rn(p2 - hf23.x, p3 - hf23.y);
            const int j = nj >> 1, e = (nj & 1) * 2;
            pah[j][e] = *(uint32_t*)&h01;
            pah[j][e + 1] = *(uint32_t*)&h23;
            pal[j][e] = *(uint32_t*)&lo01;
            pal[j][e + 1] = *(uint32_t*)&lo23;
        }
        ls0 += __shfl_xor_sync(0xffffffffu, ls0, 1);
        ls0 += __shfl_xor_sync(0xffffffffu, ls0, 2);
        ls1 += __shfl_xor_sync(0xffffffffu, ls1, 1);
        ls1 += __shfl_xor_sync(0xffffffffu, ls1, 2);
        l0r = l0r * a0 + ls0;
        l1r = l1r * a1 + ls1;

#pragma unroll
        for (int t = 0; t < 16; t++) {
            o[t][0] *= a0; o[t][1] *= a0;
            o[t][2] *= a1; o[t][3] *= a1;
        }

        // ---- O += Phi Vhi + Plo Vhi + Phi Vlo (V via ldmatrix.trans) ----
#pragma unroll
        for (int j = 0; j < 4; j++) {
#pragma unroll
            for (int nd = 0; nd < 8; nd++) {
                uint32_t vh[4], vl[4];
                const uint32_t va =
                    kvb + 2 * KV_ARR + swz(j * 16 + vRow, 2 * nd + vCh);
                ldm_x4_t(vh, va);
                ldm_x4_t(vl, va + KV_ARR);
                mma_bf16(o[2 * nd], pah[j], vh);
                mma_bf16(o[2 * nd], pal[j], vh);
                mma_bf16(o[2 * nd], pah[j], vl);
                mma_bf16(o[2 * nd + 1], pah[j], vh + 2);
                mma_bf16(o[2 * nd + 1], pal[j], vh + 2);
                mma_bf16(o[2 * nd + 1], pah[j], vl + 2);
            }
        }
        __syncthreads();
    }

    // ---- write attn_o (normalized) to g_attn [B,S,D] ----
    const float inv0 = 1.f / l0r, inv1 = 1.f / l1r;
    const int b = bh >> 4, h = bh & 15;
    const int r0g = q0 + wid * 16 + (lane >> 2);
    float* d0 = g_attn + ((size_t)(b * SLEN + r0g)) * DM + h * HS + (lane & 3) * 2;
    float* d1 = d0 + (size_t)8 * DM;
#pragma unroll
    for (int t = 0; t < 16; t++) {
        *(float2*)(d0 + t * 8) = make_float2(o[t][0] * inv0, o[t][1] * inv0);
        *(float2*)(d1 + t * 8) = make_float2(o[t][2] * inv1, o[t][3] * inv1);
    }
}

// ---------------------------------------------------------------------------
extern "C" void kernel_launch(void* const* d_in, const int* in_sizes, int n_in,
                              void* d_out, int out_size)
{
    const float* x      = (const float*)d_in[0];
    const float* w_proj = (const float*)d_in[1];
    const float* b_proj = (const float*)d_in[2];
    const float* w_ff   = (const float*)d_in[3];
    const float* b_ff   = (const float*)d_in[4];

    float* out = (float*)d_out;
    float* ff   = out;
    float* kout = out + (size_t)BATCH * SLEN * DM;
    float* vout = kout + (size_t)BATCH * NHEAD * SLEN * HS;

    cudaFuncSetAttribute(attn_mma_kernel,
                         cudaFuncAttributeMaxDynamicSharedMemorySize, ATT_SMEM);

    // 1) QKV projection: q(scaled) hi/lo -> scratch, k/v fp32 -> d_out + hi/lo
    gemm_mma_kernel<1><<<dim3(EPROJ / 128, (BATCH * SLEN) / 128), 256>>>(
        x, w_proj, b_proj, (float*)nullptr, kout, vout);

    // 2) Causal flash attention (mma.sync) -> g_attn
    attn_mma_kernel<<<dim3(SLEN / QT, BATCH * NHEAD), 256, ATT_SMEM>>>();

    // 3) FF projection -> ff output
    gemm_mma_kernel<2><<<dim3(DM / 128, (BATCH * SLEN) / 128), 256>>>(
        (const float*)nullptr, w_ff, b_ff, ff, (float*)nullptr, (float*)nullptr);
}